// round 15
// baseline (speedup 1.0000x reference)
#include <cuda_runtime.h>

// SPADE: InstanceNorm2d(affine=False) + per-pixel class-conditional affine.
// x[8,128,256,256] f32, segmap[8,20,256,256] f32, weight/bias[20,128] f32.
//
// R15 = R14 (GRID=592 full residency; best 135.4us) + R12 cache policies:
//   - stats reads __ldcg (L2-only, no L1 thrash)
//   - apply writes __stwt (write-through; no dirty L2 lines -> stats fills
//     don't collide with writebacks, more L2 capacity for x)
// plus apply micro-MLP (cls load batched with the 8 x loads).
//   phase 0:   [200 blocks] stats(img 0)  || [392 blocks] argmax
//   phase k:   [200 blocks] stats(img k)  || [392 blocks] apply(img k-1)
//   tail:      [392 blocks] apply(img 7)

#define N_   8
#define C_   128
#define H_   256
#define W_   256
#define L_   20
#define HW_  (H_ * W_)      // 65536
#define EPS_ 1e-5f

#define GRID    592          // 148 SMs * 4 blocks (exact residency)
#define THREADS 256
#define SB      200          // stats blocks
#define AB      (GRID - SB)  // 392 apply blocks
#define CGRP    8            // channels per apply item
#define WB_STRIDE 129        // full-table padded stride

// Quarter-plane partials (sum, sumsq), double-buffered by image parity.
__device__ float2 g_part[2][C_ * 4];
// Per-pixel argmax class id.
__device__ unsigned char g_cls[N_ * HW_];   // 512 KB
// Grid barrier: g_gen monotonic across launches/replays.
__device__ unsigned int g_count = 0;
__device__ unsigned int g_gen   = 0;

// ---------------------------------------------------------------------------
__device__ __forceinline__ void grid_barrier() {
    __syncthreads();
    if (threadIdx.x == 0) {
        unsigned int snap = *(volatile unsigned int*)&g_gen;
        __threadfence();
        unsigned int t = atomicAdd(&g_count, 1u);
        if (t == GRID - 1) {
            atomicExch(&g_count, 0u);
            __threadfence();
            atomicAdd(&g_gen, 1u);
        } else {
            while (*(volatile unsigned int*)&g_gen == snap) { __nanosleep(64); }
        }
        __threadfence();
    }
    __syncthreads();
}

// ---------------------------------------------------------------------------
// Stats item s in [0,512): plane c = s>>2, quarter q = s&3 (16384 floats).
// __ldcg: allocate in L2 only (the reuse consumer is the next phase's apply,
// which reads via L2; L1 allocation is pure thrash).
// ---------------------------------------------------------------------------
__device__ __forceinline__ void do_stats_item(const float* __restrict__ x, int n, int s) {
    const int c = s >> 2;
    const int q = s & 3;
    const float4* __restrict__ p =
        reinterpret_cast<const float4*>(x + (size_t)(n * C_ + c) * HW_) + q * 4096;

    float sm = 0.f, s2 = 0.f;
    #pragma unroll
    for (int i = 0; i < 16; i++) {             // 16 * 256 = 4096 float4
        float4 v = __ldcg(p + i * 256 + threadIdx.x);
        sm += (v.x + v.y) + (v.z + v.w);
        s2 += v.x * v.x + v.y * v.y + v.z * v.z + v.w * v.w;
    }
    #pragma unroll
    for (int o = 16; o > 0; o >>= 1) {
        sm += __shfl_down_sync(0xFFFFFFFFu, sm, o);
        s2 += __shfl_down_sync(0xFFFFFFFFu, s2, o);
    }
    __shared__ float ss[8], ss2[8];
    const int wid = threadIdx.x >> 5, lid = threadIdx.x & 31;
    if (lid == 0) { ss[wid] = sm; ss2[wid] = s2; }
    __syncthreads();
    if (threadIdx.x == 0) {
        float ts = 0.f, ts2 = 0.f;
        #pragma unroll
        for (int i = 0; i < 8; i++) { ts += ss[i]; ts2 += ss2[i]; }
        g_part[n & 1][c * 4 + q] = make_float2(ts, ts2);
    }
    __syncthreads();
}

// ---------------------------------------------------------------------------
// Argmax item i in [0,512): 1024 consecutive pixels (thread = float4).
// ---------------------------------------------------------------------------
__device__ __forceinline__ void do_argmax_item(const float* __restrict__ seg, int i) {
    const int idx = i * THREADS + threadIdx.x;           // 0 .. 131071
    const int n   = idx >> 14;
    const int p4  = idx & 16383;
    const float4* __restrict__ s =
        reinterpret_cast<const float4*>(seg + (size_t)n * L_ * HW_) + p4;

    float4 best = __ldcs(s);
    int b0 = 0, b1 = 0, b2 = 0, b3 = 0;
    #pragma unroll
    for (int l = 1; l < L_; l++) {
        float4 v = __ldcs(s + (size_t)l * (HW_ / 4));
        if (v.x > best.x) { best.x = v.x; b0 = l; }
        if (v.y > best.y) { best.y = v.y; b1 = l; }
        if (v.z > best.z) { best.z = v.z; b2 = l; }
        if (v.w > best.w) { best.w = v.w; b3 = l; }
    }
    *reinterpret_cast<uchar4*>(g_cls + (size_t)n * HW_ + p4 * 4) =
        make_uchar4((unsigned char)b0, (unsigned char)b1,
                    (unsigned char)b2, (unsigned char)b3);
}

// ---------------------------------------------------------------------------
// Apply item a in [0,1024): cgroup = a&15 (8 channels), slab = a>>4 (4 rows).
// x reads: __ldcs (L2 hit from stats phase, evict-first).
// out writes: __stwt (write-through, zero L2 pollution).
// cls + 8 x loads issued as one front batch (9 outstanding).
// ---------------------------------------------------------------------------
__device__ __forceinline__ void do_apply_item(
    const float* __restrict__ x, float* __restrict__ out,
    const float2* __restrict__ s_wb, const float2* __restrict__ s_ms,
    int n, int a)
{
    const int c0  = (a & 15) * CGRP;
    const int h0  = (a >> 4) << 2;
    const int tid = threadIdx.x;

    const int r    = tid >> 6;
    const int col4 = (tid & 63) << 2;
    const int pix  = (h0 + r) * W_ + col4;

    const float* __restrict__ xn = x   + (size_t)(n * C_ + c0) * HW_ + pix;
    float*       __restrict__ on = out + (size_t)(n * C_ + c0) * HW_ + pix;

    // Front-batch: cls + all 8 x loads in flight together.
    const uchar4 cl = __ldg(reinterpret_cast<const uchar4*>(g_cls + (size_t)n * HW_ + pix));
    float4 v[CGRP];
    #pragma unroll
    for (int c = 0; c < CGRP; c++)
        v[c] = __ldcs(reinterpret_cast<const float4*>(xn + (size_t)c * HW_));

    const int i0 = cl.x * WB_STRIDE + c0, i1 = cl.y * WB_STRIDE + c0,
              i2 = cl.z * WB_STRIDE + c0, i3 = cl.w * WB_STRIDE + c0;

    #pragma unroll
    for (int c = 0; c < CGRP; c++) {
        const float2 ms = s_ms[c0 + c];
        const float2 w0 = s_wb[i0 + c];
        const float2 w1 = s_wb[i1 + c];
        const float2 w2 = s_wb[i2 + c];
        const float2 w3 = s_wb[i3 + c];
        float4 o;
        o.x = fmaf((v[c].x - ms.x) * ms.y, w0.x, w0.y);
        o.y = fmaf((v[c].y - ms.x) * ms.y, w1.x, w1.y);
        o.z = fmaf((v[c].z - ms.x) * ms.y, w2.x, w2.y);
        o.w = fmaf((v[c].w - ms.x) * ms.y, w3.x, w3.y);
        __stwt(reinterpret_cast<float4*>(on + (size_t)c * HW_), o);
    }
}

// ---------------------------------------------------------------------------
__device__ __forceinline__ void finalize_stats(float2* s_ms, int n) {
    if (threadIdx.x < C_) {
        const float2* pp = &g_part[n & 1][threadIdx.x * 4];
        float ts  = (pp[0].x + pp[1].x) + (pp[2].x + pp[3].x);
        float ts2 = (pp[0].y + pp[1].y) + (pp[2].y + pp[3].y);
        const float inv_hw = 1.0f / (float)HW_;
        float mean = ts * inv_hw;
        float var  = ts2 * inv_hw - mean * mean;
        if (var < 0.f) var = 0.f;
        s_ms[threadIdx.x] = make_float2(mean, rsqrtf(var + EPS_));
    }
    __syncthreads();
}

// ---------------------------------------------------------------------------
__global__ void __launch_bounds__(THREADS, 4) spade_fused_kernel(
    const float* __restrict__ x,
    const float* __restrict__ seg,
    const float* __restrict__ wgt,
    const float* __restrict__ bia,
    float* __restrict__ out)
{
    __shared__ float2 s_wb[L_ * WB_STRIDE];   // full merged (w,b) table
    __shared__ float2 s_ms[C_];               // per-channel (mean, invstd)

    const int b = blockIdx.x;
    const bool is_stats = (b < SB);
    const int b2 = b - SB;

    // Stage the full (w,b) table once.
    for (int i = threadIdx.x; i < L_ * C_; i += THREADS) {
        int l = i >> 7, c = i & (C_ - 1);
        s_wb[l * WB_STRIDE + c] = make_float2(__ldg(wgt + i), __ldg(bia + i));
    }

    // Phase 0: stats(0) || argmax
    if (is_stats) {
        for (int s = b; s < 512; s += SB) do_stats_item(x, 0, s);
    } else {
        for (int i = b2; i < 512; i += AB) do_argmax_item(seg, i);
    }
    grid_barrier();

    // Phases 1..7: stats(k) || apply(k-1)
    for (int k = 1; k < N_; k++) {
        if (is_stats) {
            for (int s = b; s < 512; s += SB) do_stats_item(x, k, s);
        } else {
            finalize_stats(s_ms, k - 1);
            for (int a = b2; a < 1024; a += AB)
                do_apply_item(x, out, s_wb, s_ms, k - 1, a);
        }
        grid_barrier();
    }

    // Tail: apply(7)
    if (!is_stats) {
        finalize_stats(s_ms, N_ - 1);
        for (int a = b2; a < 1024; a += AB)
            do_apply_item(x, out, s_wb, s_ms, N_ - 1, a);
    }
}

// ---------------------------------------------------------------------------
extern "C" void kernel_launch(void* const* d_in, const int* in_sizes, int n_in,
                              void* d_out, int out_size) {
    const float* x   = (const float*)d_in[0];
    const float* seg = (const float*)d_in[1];
    const float* wgt = (const float*)d_in[2];
    const float* bia = (const float*)d_in[3];
    float* out = (float*)d_out;

    spade_fused_kernel<<<GRID, THREADS>>>(x, seg, wgt, bia, out);
}

// round 16
// speedup vs baseline: 1.0133x; 1.0133x over previous
#include <cuda_runtime.h>

// SPADE: InstanceNorm2d(affine=False) + per-pixel class-conditional affine.
// x[8,128,256,256] f32, segmap[8,20,256,256] f32, weight/bias[20,128] f32.
//
// R16 = R14 (GRID=592 full residency, SB=200, ldg/ldcs/stcs; best 135.4us)
// + PER-ROLE work stealing inside each phase: stats blocks steal stats
// items, apply blocks steal apply items (one atomic per item). Collapses
// the per-phase slow-SM tail to single-item granularity.
//   phase 0:   [200 blocks] stats(img 0)  || [392 blocks] argmax
//   phase k:   [200 blocks] stats(img k)  || [392 blocks] apply(img k-1)
//   tail:      [392 blocks] apply(img 7)

#define N_   8
#define C_   128
#define H_   256
#define W_   256
#define L_   20
#define HW_  (H_ * W_)      // 65536
#define EPS_ 1e-5f

#define GRID    592          // 148 SMs * 4 blocks (exact residency)
#define THREADS 256
#define SB      200          // stats blocks
#define AB      (GRID - SB)  // 392 apply blocks
#define CGRP    8            // channels per apply item
#define WB_STRIDE 129        // full-table padded stride

// Quarter-plane partials (sum, sumsq), double-buffered by image parity.
__device__ float2 g_part[2][C_ * 4];
// Per-pixel argmax class id.
__device__ unsigned char g_cls[N_ * HW_];   // 512 KB
// Grid barrier: g_gen monotonic across launches/replays.
__device__ unsigned int g_count = 0;
__device__ unsigned int g_gen   = 0;
// Ticket counters: [0..7] stats(img k), [8] argmax, [9..16] apply(img k-1)
// for k=1..7 at [9+k-1], tail apply(img 7) at [16]. Zero-init; reset by
// barrier masters (replay-safe).
__device__ unsigned int g_tk[17] = {0};

// ---------------------------------------------------------------------------
// Barrier closing phase p (p=0..7). Master resets the counters consumed in
// phase p. Barrier 0 also resets the tail counter [16]: the previous
// launch/replay's tail completed before kernel exit, so this is safe.
// ---------------------------------------------------------------------------
__device__ __forceinline__ void grid_barrier(int p) {
    __syncthreads();
    if (threadIdx.x == 0) {
        unsigned int snap = *(volatile unsigned int*)&g_gen;
        __threadfence();
        unsigned int t = atomicAdd(&g_count, 1u);
        if (t == GRID - 1) {
            atomicExch(&g_count, 0u);
            atomicExch(&g_tk[p], 0u);              // stats counter of phase p
            if (p == 0) { atomicExch(&g_tk[8], 0u); atomicExch(&g_tk[16], 0u); }
            else        { atomicExch(&g_tk[8 + p], 0u); }   // apply counter
            __threadfence();
            atomicAdd(&g_gen, 1u);
        } else {
            while (*(volatile unsigned int*)&g_gen == snap) { __nanosleep(64); }
        }
        __threadfence();
    }
    __syncthreads();
}

// ---------------------------------------------------------------------------
// Stats item s in [0,512): plane c = s>>2, quarter q = s&3 (16384 floats).
// Cached loads -> x_n resident in L2 for next phase's apply.
// ---------------------------------------------------------------------------
__device__ __forceinline__ void do_stats_item(const float* __restrict__ x, int n, int s) {
    const int c = s >> 2;
    const int q = s & 3;
    const float4* __restrict__ p =
        reinterpret_cast<const float4*>(x + (size_t)(n * C_ + c) * HW_) + q * 4096;

    float sm = 0.f, s2 = 0.f;
    #pragma unroll
    for (int i = 0; i < 16; i++) {             // 16 * 256 = 4096 float4
        float4 v = __ldg(p + i * 256 + threadIdx.x);
        sm += (v.x + v.y) + (v.z + v.w);
        s2 += v.x * v.x + v.y * v.y + v.z * v.z + v.w * v.w;
    }
    #pragma unroll
    for (int o = 16; o > 0; o >>= 1) {
        sm += __shfl_down_sync(0xFFFFFFFFu, sm, o);
        s2 += __shfl_down_sync(0xFFFFFFFFu, s2, o);
    }
    __shared__ float ss[8], ss2[8];
    const int wid = threadIdx.x >> 5, lid = threadIdx.x & 31;
    if (lid == 0) { ss[wid] = sm; ss2[wid] = s2; }
    __syncthreads();
    if (threadIdx.x == 0) {
        float ts = 0.f, ts2 = 0.f;
        #pragma unroll
        for (int i = 0; i < 8; i++) { ts += ss[i]; ts2 += ss2[i]; }
        g_part[n & 1][c * 4 + q] = make_float2(ts, ts2);
    }
    __syncthreads();
}

// ---------------------------------------------------------------------------
// Argmax item i in [0,512): 1024 consecutive pixels (thread = float4).
// ---------------------------------------------------------------------------
__device__ __forceinline__ void do_argmax_item(const float* __restrict__ seg, int i) {
    const int idx = i * THREADS + threadIdx.x;           // 0 .. 131071
    const int n   = idx >> 14;
    const int p4  = idx & 16383;
    const float4* __restrict__ s =
        reinterpret_cast<const float4*>(seg + (size_t)n * L_ * HW_) + p4;

    float4 best = __ldcs(s);
    int b0 = 0, b1 = 0, b2 = 0, b3 = 0;
    #pragma unroll
    for (int l = 1; l < L_; l++) {
        float4 v = __ldcs(s + (size_t)l * (HW_ / 4));
        if (v.x > best.x) { best.x = v.x; b0 = l; }
        if (v.y > best.y) { best.y = v.y; b1 = l; }
        if (v.z > best.z) { best.z = v.z; b2 = l; }
        if (v.w > best.w) { best.w = v.w; b3 = l; }
    }
    *reinterpret_cast<uchar4*>(g_cls + (size_t)n * HW_ + p4 * 4) =
        make_uchar4((unsigned char)b0, (unsigned char)b1,
                    (unsigned char)b2, (unsigned char)b3);
}

// ---------------------------------------------------------------------------
// Apply item a in [0,1024): cgroup = a&15 (8 channels), slab = a>>4 (4 rows).
// x reads: __ldcs (L2 hit from stats phase, evict-first). out: __stcs.
// cls + 8 x loads issued as one front batch.
// ---------------------------------------------------------------------------
__device__ __forceinline__ void do_apply_item(
    const float* __restrict__ x, float* __restrict__ out,
    const float2* __restrict__ s_wb, const float2* __restrict__ s_ms,
    int n, int a)
{
    const int c0  = (a & 15) * CGRP;
    const int h0  = (a >> 4) << 2;
    const int tid = threadIdx.x;

    const int r    = tid >> 6;
    const int col4 = (tid & 63) << 2;
    const int pix  = (h0 + r) * W_ + col4;

    const float* __restrict__ xn = x   + (size_t)(n * C_ + c0) * HW_ + pix;
    float*       __restrict__ on = out + (size_t)(n * C_ + c0) * HW_ + pix;

    const uchar4 cl = __ldg(reinterpret_cast<const uchar4*>(g_cls + (size_t)n * HW_ + pix));
    float4 v[CGRP];
    #pragma unroll
    for (int c = 0; c < CGRP; c++)
        v[c] = __ldcs(reinterpret_cast<const float4*>(xn + (size_t)c * HW_));

    const int i0 = cl.x * WB_STRIDE + c0, i1 = cl.y * WB_STRIDE + c0,
              i2 = cl.z * WB_STRIDE + c0, i3 = cl.w * WB_STRIDE + c0;

    #pragma unroll
    for (int c = 0; c < CGRP; c++) {
        const float2 ms = s_ms[c0 + c];
        const float2 w0 = s_wb[i0 + c];
        const float2 w1 = s_wb[i1 + c];
        const float2 w2 = s_wb[i2 + c];
        const float2 w3 = s_wb[i3 + c];
        float4 o;
        o.x = fmaf((v[c].x - ms.x) * ms.y, w0.x, w0.y);
        o.y = fmaf((v[c].y - ms.x) * ms.y, w1.x, w1.y);
        o.z = fmaf((v[c].z - ms.x) * ms.y, w2.x, w2.y);
        o.w = fmaf((v[c].w - ms.x) * ms.y, w3.x, w3.y);
        __stcs(reinterpret_cast<float4*>(on + (size_t)c * HW_), o);
    }
}

// ---------------------------------------------------------------------------
__device__ __forceinline__ void finalize_stats(float2* s_ms, int n) {
    if (threadIdx.x < C_) {
        const float2* pp = &g_part[n & 1][threadIdx.x * 4];
        float ts  = (pp[0].x + pp[1].x) + (pp[2].x + pp[3].x);
        float ts2 = (pp[0].y + pp[1].y) + (pp[2].y + pp[3].y);
        const float inv_hw = 1.0f / (float)HW_;
        float mean = ts * inv_hw;
        float var  = ts2 * inv_hw - mean * mean;
        if (var < 0.f) var = 0.f;
        s_ms[threadIdx.x] = make_float2(mean, rsqrtf(var + EPS_));
    }
    __syncthreads();
}

// ---------------------------------------------------------------------------
// Steal items from counter g_tk[cid] until limit; run fn(item).
// ---------------------------------------------------------------------------
#define STEAL_LOOP(cid, limit, BODY)                              \
    for (;;) {                                                    \
        __syncthreads();                                          \
        if (threadIdx.x == 0) s_t = atomicAdd(&g_tk[cid], 1u);    \
        __syncthreads();                                          \
        const unsigned int t_ = s_t;                              \
        if (t_ >= (unsigned)(limit)) break;                       \
        BODY;                                                     \
    }

__global__ void __launch_bounds__(THREADS, 4) spade_fused_kernel(
    const float* __restrict__ x,
    const float* __restrict__ seg,
    const float* __restrict__ wgt,
    const float* __restrict__ bia,
    float* __restrict__ out)
{
    __shared__ float2 s_wb[L_ * WB_STRIDE];   // full merged (w,b) table
    __shared__ float2 s_ms[C_];               // per-channel (mean, invstd)
    __shared__ unsigned int s_t;

    const int b = blockIdx.x;
    const bool is_stats = (b < SB);

    // Stage the full (w,b) table once.
    for (int i = threadIdx.x; i < L_ * C_; i += THREADS) {
        int l = i >> 7, c = i & (C_ - 1);
        s_wb[l * WB_STRIDE + c] = make_float2(__ldg(wgt + i), __ldg(bia + i));
    }

    // Phase 0: stats(0) || argmax (per-role stealing)
    if (is_stats) {
        STEAL_LOOP(0, 512, do_stats_item(x, 0, (int)t_))
    } else {
        STEAL_LOOP(8, 512, do_argmax_item(seg, (int)t_))
    }
    grid_barrier(0);

    // Phases 1..7: stats(k) || apply(k-1)
    for (int k = 1; k < N_; k++) {
        if (is_stats) {
            STEAL_LOOP(k, 512, do_stats_item(x, k, (int)t_))
        } else {
            finalize_stats(s_ms, k - 1);
            STEAL_LOOP(8 + k, 1024, do_apply_item(x, out, s_wb, s_ms, k - 1, (int)t_))
        }
        grid_barrier(k);
    }

    // Tail: apply(7), stolen from counter [16] (reset at barrier 0).
    if (!is_stats) {
        finalize_stats(s_ms, N_ - 1);
        STEAL_LOOP(16, 1024, do_apply_item(x, out, s_wb, s_ms, N_ - 1, (int)t_))
    }
}

// ---------------------------------------------------------------------------
extern "C" void kernel_launch(void* const* d_in, const int* in_sizes, int n_in,
                              void* d_out, int out_size) {
    const float* x   = (const float*)d_in[0];
    const float* seg = (const float*)d_in[1];
    const float* wgt = (const float*)d_in[2];
    const float* bia = (const float*)d_in[3];
    float* out = (float*)d_out;

    spade_fused_kernel<<<GRID, THREADS>>>(x, seg, wgt, bia, out);
}

// round 17
// speedup vs baseline: 1.2650x; 1.2484x over previous
#include <cuda_runtime.h>

// SPADE: InstanceNorm2d(affine=False) + per-pixel class-conditional affine.
// x[8,128,256,256] f32, segmap[8,20,256,256] f32, weight/bias[20,128] f32.
//
// R17: SELF-CONTAINED plane blocks — zero global coordination.
//   argmax kernel (once) -> uchar cls map.
//   plane kernel: 1024 blocks, one per (n,c) plane (256 KB), 512 threads,
//   2 blocks/SM (capped by 96 KB dynamic smem):
//     pass 1: read plane from DRAM, accumulate mean/var (block-local
//             reduction), buffering the first 96 KB in smem.
//     pass 2: re-read (96 KB from smem, 160 KB from L2 — working set
//             296 x 160 KB = 47 MB << L2), apply, stream writes.
// No grid barriers, no device-global stats roundtrip, no phase drains.

#define N_   8
#define C_   128
#define H_   256
#define W_   256
#define L_   20
#define HW_  (H_ * W_)      // 65536
#define EPS_ 1e-5f

#define PTHREADS 512
#define NIT      32          // 16384 float4 / 512 threads
#define NBUF     12          // first 12 iters (6144 float4 = 96 KB) in smem
#define DYN_SMEM (NBUF * PTHREADS * 16)   // 98304 B

// Per-pixel argmax class id.
__device__ unsigned char g_cls[N_ * HW_];   // 512 KB

// ---------------------------------------------------------------------------
// Argmax: thread = 4 adjacent pixels (float4 per plane). Grid 512.
// ---------------------------------------------------------------------------
__global__ void __launch_bounds__(256) spade_argmax_kernel(const float* __restrict__ seg) {
    const int idx = blockIdx.x * 256 + threadIdx.x;     // over N*HW/4
    const int n   = idx >> 14;
    const int p4  = idx & 16383;
    const float4* __restrict__ s =
        reinterpret_cast<const float4*>(seg + (size_t)n * L_ * HW_) + p4;

    float4 best = __ldcs(s);
    int b0 = 0, b1 = 0, b2 = 0, b3 = 0;
    #pragma unroll
    for (int l = 1; l < L_; l++) {
        float4 v = __ldcs(s + (size_t)l * (HW_ / 4));
        if (v.x > best.x) { best.x = v.x; b0 = l; }
        if (v.y > best.y) { best.y = v.y; b1 = l; }
        if (v.z > best.z) { best.z = v.z; b2 = l; }
        if (v.w > best.w) { best.w = v.w; b3 = l; }
    }
    *reinterpret_cast<uchar4*>(g_cls + (size_t)n * HW_ + p4 * 4) =
        make_uchar4((unsigned char)b0, (unsigned char)b1,
                    (unsigned char)b2, (unsigned char)b3);
}

// ---------------------------------------------------------------------------
// Plane kernel: block = one (n,c) plane.
// ---------------------------------------------------------------------------
__global__ void __launch_bounds__(PTHREADS, 2) spade_plane_kernel(
    const float* __restrict__ x,
    const float* __restrict__ wgt,
    const float* __restrict__ bia,
    float* __restrict__ out)
{
    extern __shared__ float4 sb[];            // 6144 float4 plane buffer
    __shared__ float2 s_wb[32];               // (w,b) for channel c, 20 classes
    __shared__ float  ss[16], ss2[16];
    __shared__ float2 s_ms;

    const int plane = blockIdx.x;             // 0..1023
    const int n     = plane >> 7;
    const int c     = plane & (C_ - 1);
    const int tid   = threadIdx.x;

    // Tiny per-channel table: 20 float2.
    if (tid < L_)
        s_wb[tid] = make_float2(__ldg(wgt + tid * C_ + c), __ldg(bia + tid * C_ + c));

    const float4* __restrict__ xp =
        reinterpret_cast<const float4*>(x + (size_t)plane * HW_);

    // ---- Pass 1: read plane, accumulate, buffer first NBUF iters in smem ----
    float sm = 0.f, s2 = 0.f;
    #pragma unroll 4
    for (int i = 0; i < NIT; i++) {
        float4 v = __ldg(xp + i * PTHREADS + tid);
        if (i < NBUF) sb[i * PTHREADS + tid] = v;
        sm += (v.x + v.y) + (v.z + v.w);
        s2 += v.x * v.x + v.y * v.y + v.z * v.z + v.w * v.w;
    }
    #pragma unroll
    for (int o = 16; o > 0; o >>= 1) {
        sm += __shfl_down_sync(0xFFFFFFFFu, sm, o);
        s2 += __shfl_down_sync(0xFFFFFFFFu, s2, o);
    }
    const int wid = tid >> 5, lid = tid & 31;
    if (lid == 0) { ss[wid] = sm; ss2[wid] = s2; }
    __syncthreads();
    if (tid == 0) {
        float ts = 0.f, ts2 = 0.f;
        #pragma unroll
        for (int i = 0; i < 16; i++) { ts += ss[i]; ts2 += ss2[i]; }
        const float inv_hw = 1.0f / (float)HW_;
        float mean = ts * inv_hw;
        float var  = ts2 * inv_hw - mean * mean;
        if (var < 0.f) var = 0.f;
        s_ms = make_float2(mean, rsqrtf(var + EPS_));
    }
    __syncthreads();
    const float2 ms = s_ms;

    // ---- Pass 2: re-read (smem / L2), apply class affine, stream writes ----
    const uchar4* __restrict__ cp =
        reinterpret_cast<const uchar4*>(g_cls + (size_t)n * HW_);
    float4* __restrict__ op = reinterpret_cast<float4*>(out + (size_t)plane * HW_);

    #pragma unroll
    for (int j = 0; j < NIT / 4; j++) {
        float4 v[4]; uchar4 cl[4];
        #pragma unroll
        for (int u = 0; u < 4; u++) {
            const int i = j * 4 + u;
            if (i < NBUF) v[u] = sb[i * PTHREADS + tid];
            else          v[u] = __ldcs(xp + i * PTHREADS + tid);
            cl[u] = __ldg(cp + i * PTHREADS + tid);
        }
        #pragma unroll
        for (int u = 0; u < 4; u++) {
            const int i = j * 4 + u;
            const float2 w0 = s_wb[cl[u].x];
            const float2 w1 = s_wb[cl[u].y];
            const float2 w2 = s_wb[cl[u].z];
            const float2 w3 = s_wb[cl[u].w];
            float4 o;
            o.x = fmaf((v[u].x - ms.x) * ms.y, w0.x, w0.y);
            o.y = fmaf((v[u].y - ms.x) * ms.y, w1.x, w1.y);
            o.z = fmaf((v[u].z - ms.x) * ms.y, w2.x, w2.y);
            o.w = fmaf((v[u].w - ms.x) * ms.y, w3.x, w3.y);
            __stcs(op + i * PTHREADS + tid, o);
        }
    }
}

// ---------------------------------------------------------------------------
extern "C" void kernel_launch(void* const* d_in, const int* in_sizes, int n_in,
                              void* d_out, int out_size) {
    const float* x   = (const float*)d_in[0];
    const float* seg = (const float*)d_in[1];
    const float* wgt = (const float*)d_in[2];
    const float* bia = (const float*)d_in[3];
    float* out = (float*)d_out;

    static int smem_set = 0;
    if (!smem_set) {
        cudaFuncSetAttribute(spade_plane_kernel,
                             cudaFuncAttributeMaxDynamicSharedMemorySize, DYN_SMEM);
        smem_set = 1;
    }

    spade_argmax_kernel<<<512, 256>>>(seg);
    spade_plane_kernel<<<N_ * C_, PTHREADS, DYN_SMEM>>>(x, wgt, bia, out);
}